// round 16
// baseline (speedup 1.0000x reference)
#include <cuda_runtime.h>

#define B_ 2
#define S_ 512
#define H_ 128
#define A_ 7
#define NROW (B_*S_)
#define ACT_SZ (NROW*A_)
#define PTR_SZ (B_*S_*S_)

// Scratch (allocation-free rule: __device__ globals)
__device__ float g_act[NROW*H_];            // post gelu+LN action hidden
__device__ float g_hvT[2*B_*H_*S_];         // [head][b][h][s]  (transposed "hiddens" branch)
__device__ float g_hd [2*B_*S_*H_];         // [head][b][s][h]  ("heads" branch)
__device__ float g_logits[NROW*A_];

__device__ __forceinline__ float gelu_t(float x){
    // tanh-approx GeLU: 0.5*x*(1+tanh(x*(0.7978845608 + 0.0356774081*x^2)))
    float x2  = x*x;
    float u   = fmaf(0.0356774081f, x2, 0.7978845608f);
    float arg = x*u;
    float th;
    asm("tanh.approx.f32 %0, %1;" : "=f"(th) : "f"(arg));
    float hx = 0.5f*x;
    return fmaf(hx, th, hx);
}

// ---------------------------------------------------------------------------
// Kernel A: the five [1024,128]x[128,128] linears.
//   m=0: aw1 -> gelu -> LN -> g_act
//   m=1: lhid_w  -> g_hvT[0] (transposed)   m=2: lhead_w -> g_hd[0]
//   m=3: rhid_w  -> g_hvT[1] (transposed)   m=4: rhead_w -> g_hd[1]
// Block = 128 threads (thread = output column h), 32 rows per block.
// ---------------------------------------------------------------------------
__global__ void __launch_bounds__(128) k_linear(
    const float* __restrict__ hid,
    const float* __restrict__ aw1, const float* __restrict__ ab1,
    const float* __restrict__ alng, const float* __restrict__ alnb,
    const float* __restrict__ w1, const float* __restrict__ b1,
    const float* __restrict__ w2, const float* __restrict__ b2,
    const float* __restrict__ w3, const float* __restrict__ b3,
    const float* __restrict__ w4, const float* __restrict__ b4)
{
    __shared__ float x_s[32*H_];
    __shared__ float red[4][8];

    int m    = blockIdx.x;
    int row0 = blockIdx.y * 32;
    const float* W; const float* bias;
    if      (m==0){ W=aw1; bias=ab1; }
    else if (m==1){ W=w1;  bias=b1;  }
    else if (m==2){ W=w2;  bias=b2;  }
    else if (m==3){ W=w3;  bias=b3;  }
    else          { W=w4;  bias=b4;  }

    int t = threadIdx.x, lane = t & 31, wd = t >> 5;
    for (int i = t; i < 32*H_; i += 128) x_s[i] = hid[row0*H_ + i];
    __syncthreads();

    float bh  = bias[t];
    float gch = 1.f, bch = 0.f;
    if (m == 0){ gch = alng[t]; bch = alnb[t]; }
    int b = row0 >> 9;

    for (int rg = 0; rg < 8; rg++){
        const float* x0 = &x_s[(rg*4+0)*H_];
        const float* x1 = x0 + H_;
        const float* x2 = x1 + H_;
        const float* x3 = x2 + H_;
        float a0=bh, a1=bh, a2=bh, a3=bh;
        #pragma unroll 8
        for (int k = 0; k < H_; k++){
            float wv = W[k*H_ + t];
            a0 = fmaf(x0[k], wv, a0);
            a1 = fmaf(x1[k], wv, a1);
            a2 = fmaf(x2[k], wv, a2);
            a3 = fmaf(x3[k], wv, a3);
        }
        int row   = row0 + rg*4;
        int sbase = (row & 511);
        if (m == 0){
            float g0=gelu_t(a0), g1=gelu_t(a1), g2=gelu_t(a2), g3=gelu_t(a3);
            float v[8] = {g0,g1,g2,g3, g0*g0,g1*g1,g2*g2,g3*g3};
            #pragma unroll
            for (int j = 0; j < 8; j++){
                float x = v[j];
                #pragma unroll
                for (int off = 16; off; off >>= 1)
                    x += __shfl_xor_sync(0xffffffffu, x, off);
                v[j] = x;
            }
            if (lane == 0){
                #pragma unroll
                for (int j = 0; j < 8; j++) red[wd][j] = v[j];
            }
            __syncthreads();
            float gg[4] = {g0,g1,g2,g3};
            #pragma unroll
            for (int r = 0; r < 4; r++){
                float s  = red[0][r]+red[1][r]+red[2][r]+red[3][r];
                float q  = red[0][r+4]+red[1][r+4]+red[2][r+4]+red[3][r+4];
                float mn = s*(1.f/128.f);
                float vr = fmaf(-mn, mn, q*(1.f/128.f));
                float rs = rsqrtf(vr + 1e-5f);
                g_act[(row+r)*H_ + t] = (gg[r]-mn)*rs*gch + bch;
            }
            __syncthreads();
        } else if (m == 1 || m == 3){
            int head = (m==1) ? 0 : 1;
            float* dst = &g_hvT[((head*B_ + b)*H_ + t)*S_ + sbase];
            *(float4*)dst = make_float4(a0, a1, a2, a3);
        } else {
            int head = (m==2) ? 0 : 1;
            float* base = &g_hd[((head*B_ + b)*S_ + sbase)*H_ + t];
            base[0*H_] = a0; base[1*H_] = a1; base[2*H_] = a2; base[3*H_] = a3;
        }
    }
}

// ---------------------------------------------------------------------------
// Kernel B1: logits[b,s,a] = g_act[b,s,:] @ aw2 + ab2   (warp per (b,s))
// ---------------------------------------------------------------------------
__global__ void __launch_bounds__(256) k_logits(
    const float* __restrict__ aw2, const float* __restrict__ ab2)
{
    int gw   = (blockIdx.x*256 + threadIdx.x) >> 5;  // 0..1023
    int lane = threadIdx.x & 31;
    float4 xv = *(const float4*)&g_act[gw*H_ + lane*4];
    int k0 = lane*4;
    #pragma unroll
    for (int a = 0; a < A_; a++){
        float p = xv.x*aw2[(k0+0)*A_+a];
        p = fmaf(xv.y, aw2[(k0+1)*A_+a], p);
        p = fmaf(xv.z, aw2[(k0+2)*A_+a], p);
        p = fmaf(xv.w, aw2[(k0+3)*A_+a], p);
        #pragma unroll
        for (int off = 16; off; off >>= 1)
            p += __shfl_xor_sync(0xffffffffu, p, off);
        if (lane == 0) g_logits[gw*A_ + a] = p + ab2[a];
    }
}

// ---------------------------------------------------------------------------
// Kernel B2: actions = log_softmax over axis=1 (sequence). Block per (b,a).
// ---------------------------------------------------------------------------
__global__ void __launch_bounds__(512) k_actsm(float* __restrict__ out)
{
    int b = blockIdx.x / A_, a = blockIdx.x % A_;
    int t = threadIdx.x, lane = t & 31, wd = t >> 5;
    __shared__ float rs[16];
    __shared__ float bmax, blse;

    float v = g_logits[(b*S_ + t)*A_ + a];

    float mx = v;
    #pragma unroll
    for (int off = 16; off; off >>= 1)
        mx = fmaxf(mx, __shfl_xor_sync(0xffffffffu, mx, off));
    if (lane == 0) rs[wd] = mx;
    __syncthreads();
    if (t == 0){
        float mm = rs[0];
        for (int i = 1; i < 16; i++) mm = fmaxf(mm, rs[i]);
        bmax = mm;
    }
    __syncthreads();

    float e = __expf(v - bmax);
    #pragma unroll
    for (int off = 16; off; off >>= 1)
        e += __shfl_xor_sync(0xffffffffu, e, off);
    if (lane == 0) rs[wd] = e;
    __syncthreads();
    if (t == 0){
        float ss = 0.f;
        for (int i = 0; i < 16; i++) ss += rs[i];
        blse = __logf(ss);
    }
    __syncthreads();

    out[(b*S_ + t)*A_ + a] = v - bmax - blse;
}

// ---------------------------------------------------------------------------
// Kernel C: pointer heads. Block = 8 warps = 8 i-rows of one (head,b).
// Warp w handles i = i0+w; lane owns j = tile*128 + 4*lane + q.
// One pass over h computes (sum, sumsq, gdot) -> fused LN+proj score.
// Then per-warp log_softmax over the 512 scores held in registers.
// ---------------------------------------------------------------------------
__global__ void __launch_bounds__(256) k_pointer(
    const float* __restrict__ lng0, const float* __restrict__ lnb0,
    const float* __restrict__ pw0,  const float* __restrict__ pb0,
    const float* __restrict__ lng1, const float* __restrict__ lnb1,
    const float* __restrict__ pw1,  const float* __restrict__ pb1,
    float* __restrict__ out)
{
    extern __shared__ float sm[];
    float* hvT_s = sm;                 // 128 rows * 132 (padded) = 16896 floats
    float* hd_s  = sm + 128*132;       // 8*128
    float* c1_s  = hd_s + 8*H_;        // 128
    float* redp  = c1_s + H_;          // 8
    float* cst   = redp + 8;           // 2

    int t = threadIdx.x, lane = t & 31, w = t >> 5;
    int ib = blockIdx.x, b = blockIdx.y, head = blockIdx.z;
    const float* lng = head ? lng1 : lng0;
    const float* lnb = head ? lnb1 : lnb0;
    const float* pw  = head ? pw1  : pw0;
    const float* pb  = head ? pb1  : pb0;
    int i0 = ib * 8;

    // c1 = lng*pw; C1 = sum(c1); Cb = sum(lnb*pw) + pb
    if (t < H_){
        float g = lng[t], p = pw[t], bb = lnb[t];
        float c  = g*p;
        c1_s[t]  = c;
        float v1 = c, v0 = bb*p;
        #pragma unroll
        for (int off = 16; off; off >>= 1){
            v1 += __shfl_xor_sync(0xffffffffu, v1, off);
            v0 += __shfl_xor_sync(0xffffffffu, v0, off);
        }
        if (lane == 0){ redp[w*2] = v1; redp[w*2+1] = v0; }
    }
    const float* hdg = g_hd + ((size_t)(head*B_ + b)*S_ + i0)*H_;
    for (int idx = t; idx < 8*H_; idx += 256) hd_s[idx] = hdg[idx];
    __syncthreads();
    if (t == 0){
        cst[0] = redp[0]+redp[2]+redp[4]+redp[6];
        cst[1] = redp[1]+redp[3]+redp[5]+redp[7] + pb[0];
    }
    __syncthreads();
    float C1 = cst[0], Cb = cst[1];

    const float* hvTb = g_hvT + (size_t)(head*B_ + b)*H_*S_;
    const float* hdw  = hd_s + w*H_;
    const float* hp0  = hvT_s + 4*lane;
    float sc[16];

    for (int tile = 0; tile < 4; tile++){
        // stage transposed tile [h][128 j], conflict-free reads/writes
        for (int r = w; r < H_; r += 8){
            float4 v = *(const float4*)(hvTb + r*S_ + tile*128 + 4*lane);
            *(float4*)(hvT_s + r*132 + 4*lane) = v;
        }
        __syncthreads();

        float s0=0,s1=0,s2=0,s3=0;
        float q0=0,q1=0,q2=0,q3=0;
        float d0=0,d1=0,d2=0,d3=0;
        #pragma unroll 4
        for (int h = 0; h < H_; h++){
            float4 v = *(const float4*)(hp0 + h*132);
            float dd = hdw[h];
            float c  = c1_s[h];
            float g;
            g = gelu_t(v.x + dd); s0 += g; q0 = fmaf(g,g,q0); d0 = fmaf(g,c,d0);
            g = gelu_t(v.y + dd); s1 += g; q1 = fmaf(g,g,q1); d1 = fmaf(g,c,d1);
            g = gelu_t(v.z + dd); s2 += g; q2 = fmaf(g,g,q2); d2 = fmaf(g,c,d2);
            g = gelu_t(v.w + dd); s3 += g; q3 = fmaf(g,g,q3); d3 = fmaf(g,c,d3);
        }
        {
            float mn, vr, rs;
            mn = s0*(1.f/128.f); vr = fmaf(-mn,mn,q0*(1.f/128.f)); rs = rsqrtf(vr+1e-5f);
            sc[tile*4+0] = rs*fmaf(-mn, C1, d0) + Cb;
            mn = s1*(1.f/128.f); vr = fmaf(-mn,mn,q1*(1.f/128.f)); rs = rsqrtf(vr+1e-5f);
            sc[tile*4+1] = rs*fmaf(-mn, C1, d1) + Cb;
            mn = s2*(1.f/128.f); vr = fmaf(-mn,mn,q2*(1.f/128.f)); rs = rsqrtf(vr+1e-5f);
            sc[tile*4+2] = rs*fmaf(-mn, C1, d2) + Cb;
            mn = s3*(1.f/128.f); vr = fmaf(-mn,mn,q3*(1.f/128.f)); rs = rsqrtf(vr+1e-5f);
            sc[tile*4+3] = rs*fmaf(-mn, C1, d3) + Cb;
        }
        __syncthreads();
    }

    // per-warp log_softmax over the 512 scores of row i
    float mx = sc[0];
    #pragma unroll
    for (int k = 1; k < 16; k++) mx = fmaxf(mx, sc[k]);
    #pragma unroll
    for (int off = 16; off; off >>= 1)
        mx = fmaxf(mx, __shfl_xor_sync(0xffffffffu, mx, off));
    float se = 0.f;
    #pragma unroll
    for (int k = 0; k < 16; k++) se += __expf(sc[k] - mx);
    #pragma unroll
    for (int off = 16; off; off >>= 1)
        se += __shfl_xor_sync(0xffffffffu, se, off);
    float lse = mx + __logf(se);

    float* orow = out + ACT_SZ + (size_t)head*PTR_SZ + (size_t)(b*S_ + i0 + w)*S_;
    #pragma unroll
    for (int tile = 0; tile < 4; tile++){
        float4 o;
        o.x = sc[tile*4+0] - lse;
        o.y = sc[tile*4+1] - lse;
        o.z = sc[tile*4+2] - lse;
        o.w = sc[tile*4+3] - lse;
        *(float4*)(orow + tile*128 + 4*lane) = o;
    }
}

// ---------------------------------------------------------------------------
extern "C" void kernel_launch(void* const* d_in, const int* in_sizes, int n_in,
                              void* d_out, int out_size)
{
    const float* hiddens = (const float*)d_in[0];
    const float* aw1     = (const float*)d_in[1];
    const float* ab1     = (const float*)d_in[2];
    const float* a_ln_g  = (const float*)d_in[3];
    const float* a_ln_b  = (const float*)d_in[4];
    const float* aw2     = (const float*)d_in[5];
    const float* ab2     = (const float*)d_in[6];
    const float* lhid_w  = (const float*)d_in[7];
    const float* lhid_b  = (const float*)d_in[8];
    const float* lhead_w = (const float*)d_in[9];
    const float* lhead_b = (const float*)d_in[10];
    const float* l_ln_g  = (const float*)d_in[11];
    const float* l_ln_b  = (const float*)d_in[12];
    const float* l_pw    = (const float*)d_in[13];
    const float* l_pb    = (const float*)d_in[14];
    const float* rhid_w  = (const float*)d_in[15];
    const float* rhid_b  = (const float*)d_in[16];
    const float* rhead_w = (const float*)d_in[17];
    const float* rhead_b = (const float*)d_in[18];
    const float* r_ln_g  = (const float*)d_in[19];
    const float* r_ln_b  = (const float*)d_in[20];
    const float* r_pw    = (const float*)d_in[21];
    const float* r_pb    = (const float*)d_in[22];
    float* out = (float*)d_out;

    size_t smemC = (size_t)(128*132 + 8*H_ + H_ + 8 + 2) * sizeof(float); // ~72.3 KB
    cudaFuncSetAttribute(k_pointer, cudaFuncAttributeMaxDynamicSharedMemorySize, (int)smemC);

    k_linear<<<dim3(5,32), 128>>>(hiddens, aw1, ab1, a_ln_g, a_ln_b,
                                  lhid_w, lhid_b, lhead_w, lhead_b,
                                  rhid_w, rhid_b, rhead_w, rhead_b);
    k_logits<<<128, 256>>>(aw2, ab2);
    k_actsm<<<B_*A_, 512>>>(out);
    k_pointer<<<dim3(64, B_, 2), 256, smemC>>>(l_ln_g, l_ln_b, l_pw, l_pb,
                                               r_ln_g, r_ln_b, r_pw, r_pb, out);
}

// round 17
// speedup vs baseline: 1.5756x; 1.5756x over previous
#include <cuda_runtime.h>

#define B_ 2
#define S_ 512
#define H_ 128
#define A_ 7
#define NROW (B_*S_)
#define ACT_SZ (NROW*A_)
#define PTR_SZ (B_*S_*S_)

typedef unsigned long long ull;

// Scratch (allocation-free rule: __device__ globals)
__device__ float g_act[NROW*H_];            // post gelu+LN action hidden
__device__ float g_hvT[2*B_*H_*S_];         // [head][b][h][s]  (transposed "hiddens" branch)
__device__ float g_hd [2*B_*S_*H_];         // [head][b][s][h]  ("heads" branch)
__device__ float g_logits[NROW*A_];

__device__ __forceinline__ float gelu_t(float x){
    float x2  = x*x;
    float u   = fmaf(0.0356774081f, x2, 0.7978845608f);
    float arg = x*u;
    float th;
    asm("tanh.approx.f32 %0, %1;" : "=f"(th) : "f"(arg));
    float hx = 0.5f*x;
    return fmaf(hx, th, hx);
}

// ---- packed f32x2 helpers (FFMA2 path, sm_100+) ----
__device__ __forceinline__ ull pack2(float a, float b){
    ull r; asm("mov.b64 %0, {%1, %2};" : "=l"(r) : "f"(a), "f"(b)); return r;
}
__device__ __forceinline__ float2 unpack2(ull v){
    float2 r; asm("mov.b64 {%0, %1}, %2;" : "=f"(r.x), "=f"(r.y) : "l"(v)); return r;
}
__device__ __forceinline__ ull add2(ull a, ull b){
    ull r; asm("add.rn.f32x2 %0, %1, %2;" : "=l"(r) : "l"(a), "l"(b)); return r;
}
__device__ __forceinline__ ull mul2(ull a, ull b){
    ull r; asm("mul.rn.f32x2 %0, %1, %2;" : "=l"(r) : "l"(a), "l"(b)); return r;
}
__device__ __forceinline__ ull fma2(ull a, ull b, ull c){
    ull r; asm("fma.rn.f32x2 %0, %1, %2, %3;" : "=l"(r) : "l"(a), "l"(b), "l"(c)); return r;
}
__device__ __forceinline__ ull gelu2(ull x, ull C0, ull C1, ull HF){
    ull x2  = mul2(x, x);
    ull u   = fma2(C1, x2, C0);
    ull arg = mul2(x, u);
    float2 a = unpack2(arg);
    float t0, t1;
    asm("tanh.approx.f32 %0, %1;" : "=f"(t0) : "f"(a.x));
    asm("tanh.approx.f32 %0, %1;" : "=f"(t1) : "f"(a.y));
    ull th = pack2(t0, t1);
    ull hx = mul2(HF, x);
    return fma2(hx, th, hx);
}

// ---------------------------------------------------------------------------
// Kernel A: the five [1024,128]x[128,128] linears.
// Block = 128 threads (thread = output col t), 16 rows per block, 16 accums.
// W loaded ONCE per k (amortized over 16 rows); x staged transposed in smem.
// grid = (5 m, 64 rowchunks)
// ---------------------------------------------------------------------------
__global__ void __launch_bounds__(128) k_linear(
    const float* __restrict__ hid,
    const float* __restrict__ aw1, const float* __restrict__ ab1,
    const float* __restrict__ alng, const float* __restrict__ alnb,
    const float* __restrict__ w1, const float* __restrict__ b1,
    const float* __restrict__ w2, const float* __restrict__ b2,
    const float* __restrict__ w3, const float* __restrict__ b3,
    const float* __restrict__ w4, const float* __restrict__ b4)
{
    __shared__ float xT[128*20];      // [k][r], pitch 20 (16B-aligned float4 groups)
    __shared__ float red[4][32];      // LN partials: [warp][row 0..15 sum, 16..31 sumsq]

    int m    = blockIdx.x;
    int row0 = blockIdx.y * 16;
    const float* W; const float* bias;
    if      (m==0){ W=aw1; bias=ab1; }
    else if (m==1){ W=w1;  bias=b1;  }
    else if (m==2){ W=w2;  bias=b2;  }
    else if (m==3){ W=w3;  bias=b3;  }
    else          { W=w4;  bias=b4;  }

    int t = threadIdx.x, lane = t & 31, wd = t >> 5;

    // stage x transposed: xT[k*20 + r] = hid[(row0+r)*128 + k]
    for (int i = t; i < 16*H_; i += 128){
        int r = i >> 7, k = i & 127;
        xT[k*20 + r] = hid[(row0 + r)*H_ + k];
    }
    __syncthreads();

    float bh = bias[t];
    float acc[16];
    #pragma unroll
    for (int r = 0; r < 16; r++) acc[r] = bh;

    #pragma unroll 4
    for (int k = 0; k < H_; k++){
        float wv = W[k*H_ + t];
        const float4* xk = (const float4*)&xT[k*20];
        float4 xa = xk[0], xb = xk[1], xc = xk[2], xd = xk[3];
        acc[ 0] = fmaf(xa.x, wv, acc[ 0]);
        acc[ 1] = fmaf(xa.y, wv, acc[ 1]);
        acc[ 2] = fmaf(xa.z, wv, acc[ 2]);
        acc[ 3] = fmaf(xa.w, wv, acc[ 3]);
        acc[ 4] = fmaf(xb.x, wv, acc[ 4]);
        acc[ 5] = fmaf(xb.y, wv, acc[ 5]);
        acc[ 6] = fmaf(xb.z, wv, acc[ 6]);
        acc[ 7] = fmaf(xb.w, wv, acc[ 7]);
        acc[ 8] = fmaf(xc.x, wv, acc[ 8]);
        acc[ 9] = fmaf(xc.y, wv, acc[ 9]);
        acc[10] = fmaf(xc.z, wv, acc[10]);
        acc[11] = fmaf(xc.w, wv, acc[11]);
        acc[12] = fmaf(xd.x, wv, acc[12]);
        acc[13] = fmaf(xd.y, wv, acc[13]);
        acc[14] = fmaf(xd.z, wv, acc[14]);
        acc[15] = fmaf(xd.w, wv, acc[15]);
    }

    int b     = row0 >> 9;
    int sbase = row0 & 511;

    if (m == 0){
        float gch = alng[t], bch = alnb[t];
        #pragma unroll
        for (int r = 0; r < 16; r++){
            float g = gelu_t(acc[r]);
            acc[r]  = g;
            float s = g, q = g*g;
            #pragma unroll
            for (int off = 16; off; off >>= 1){
                s += __shfl_xor_sync(0xffffffffu, s, off);
                q += __shfl_xor_sync(0xffffffffu, q, off);
            }
            if (lane == 0){ red[wd][r] = s; red[wd][16+r] = q; }
        }
        __syncthreads();
        #pragma unroll
        for (int r = 0; r < 16; r++){
            float s  = red[0][r]+red[1][r]+red[2][r]+red[3][r];
            float q  = red[0][16+r]+red[1][16+r]+red[2][16+r]+red[3][16+r];
            float mn = s*(1.f/128.f);
            float vr = fmaf(-mn, mn, q*(1.f/128.f));
            float rs = rsqrtf(vr + 1e-5f);
            g_act[(row0+r)*H_ + t] = (acc[r]-mn)*rs*gch + bch;
        }
    } else if (m == 1 || m == 3){
        int head = (m==1) ? 0 : 1;
        float* dst = &g_hvT[((head*B_ + b)*H_ + t)*S_ + sbase];
        #pragma unroll
        for (int g4 = 0; g4 < 4; g4++)
            *(float4*)(dst + g4*4) = make_float4(acc[g4*4], acc[g4*4+1],
                                                 acc[g4*4+2], acc[g4*4+3]);
    } else {
        int head = (m==2) ? 0 : 1;
        float* base = &g_hd[((head*B_ + b)*S_ + sbase)*H_ + t];
        #pragma unroll
        for (int r = 0; r < 16; r++) base[r*H_] = acc[r];
    }
}

// ---------------------------------------------------------------------------
// Kernel B1: logits[b,s,a] = g_act[b,s,:] @ aw2 + ab2   (warp per (b,s))
// ---------------------------------------------------------------------------
__global__ void __launch_bounds__(256) k_logits(
    const float* __restrict__ aw2, const float* __restrict__ ab2)
{
    int gw   = (blockIdx.x*256 + threadIdx.x) >> 5;  // 0..1023
    int lane = threadIdx.x & 31;
    float4 xv = *(const float4*)&g_act[gw*H_ + lane*4];
    int k0 = lane*4;
    #pragma unroll
    for (int a = 0; a < A_; a++){
        float p = xv.x*aw2[(k0+0)*A_+a];
        p = fmaf(xv.y, aw2[(k0+1)*A_+a], p);
        p = fmaf(xv.z, aw2[(k0+2)*A_+a], p);
        p = fmaf(xv.w, aw2[(k0+3)*A_+a], p);
        #pragma unroll
        for (int off = 16; off; off >>= 1)
            p += __shfl_xor_sync(0xffffffffu, p, off);
        if (lane == 0) g_logits[gw*A_ + a] = p + ab2[a];
    }
}

// ---------------------------------------------------------------------------
// Kernel B2: actions = log_softmax over axis=1 (sequence). Block per (b,a).
// ---------------------------------------------------------------------------
__global__ void __launch_bounds__(512) k_actsm(float* __restrict__ out)
{
    int b = blockIdx.x / A_, a = blockIdx.x % A_;
    int t = threadIdx.x, lane = t & 31, wd = t >> 5;
    __shared__ float rs[16];
    __shared__ float bmax, blse;

    float v = g_logits[(b*S_ + t)*A_ + a];

    float mx = v;
    #pragma unroll
    for (int off = 16; off; off >>= 1)
        mx = fmaxf(mx, __shfl_xor_sync(0xffffffffu, mx, off));
    if (lane == 0) rs[wd] = mx;
    __syncthreads();
    if (t == 0){
        float mm = rs[0];
        for (int i = 1; i < 16; i++) mm = fmaxf(mm, rs[i]);
        bmax = mm;
    }
    __syncthreads();

    float e = __expf(v - bmax);
    #pragma unroll
    for (int off = 16; off; off >>= 1)
        e += __shfl_xor_sync(0xffffffffu, e, off);
    if (lane == 0) rs[wd] = e;
    __syncthreads();
    if (t == 0){
        float ss = 0.f;
        for (int i = 0; i < 16; i++) ss += rs[i];
        blse = __logf(ss);
    }
    __syncthreads();

    out[(b*S_ + t)*A_ + a] = v - bmax - blse;
}

// ---------------------------------------------------------------------------
// Kernel C: pointer heads, packed f32x2 math. Block = 8 warps = 8 i-rows of
// one (head,b). Warp w handles i=i0+w; lane owns j pair (4j = 2 f32x2 pairs).
// One pass over h computes (sum, sumsq, gdot) packed -> fused LN+proj score.
// ---------------------------------------------------------------------------
__global__ void __launch_bounds__(256) k_pointer(
    const float* __restrict__ lng0, const float* __restrict__ lnb0,
    const float* __restrict__ pw0,  const float* __restrict__ pb0,
    const float* __restrict__ lng1, const float* __restrict__ lnb1,
    const float* __restrict__ pw1,  const float* __restrict__ pb1,
    float* __restrict__ out)
{
    extern __shared__ float sm[];
    float* hvT_s = sm;                                  // 128*132 floats (67584 B)
    ull*   hd2_s = (ull*)(sm + 128*132);                // 8*128 packed (dd,dd)
    ull*   c2_s  = hd2_s + 8*H_;                        // 128 packed (c,c)
    float* redp  = (float*)(c2_s + H_);                 // 8
    float* cst   = redp + 8;                            // 2

    int t = threadIdx.x, lane = t & 31, w = t >> 5;
    int ib = blockIdx.x, b = blockIdx.y, head = blockIdx.z;
    const float* lng = head ? lng1 : lng0;
    const float* lnb = head ? lnb1 : lnb0;
    const float* pw  = head ? pw1  : pw0;
    const float* pb  = head ? pb1  : pb0;
    int i0 = ib * 8;

    // c = lng*pw packed-duplicated; C1 = sum(c); Cb = sum(lnb*pw) + pb
    if (t < H_){
        float g = lng[t], p = pw[t], bb = lnb[t];
        float c  = g*p;
        c2_s[t]  = pack2(c, c);
        float v1 = c, v0 = bb*p;
        #pragma unroll
        for (int off = 16; off; off >>= 1){
            v1 += __shfl_xor_sync(0xffffffffu, v1, off);
            v0 += __shfl_xor_sync(0xffffffffu, v0, off);
        }
        if (lane == 0){ redp[w*2] = v1; redp[w*2+1] = v0; }
    }
    const float* hdg = g_hd + ((size_t)(head*B_ + b)*S_ + i0)*H_;
    for (int idx = t; idx < 8*H_; idx += 256){
        float v = hdg[idx];
        hd2_s[idx] = pack2(v, v);
    }
    __syncthreads();
    if (t == 0){
        cst[0] = redp[0]+redp[2]+redp[4]+redp[6];
        cst[1] = redp[1]+redp[3]+redp[5]+redp[7] + pb[0];
    }
    __syncthreads();
    float C1 = cst[0], Cb = cst[1];

    const ull C0_2 = pack2(0.7978845608f, 0.7978845608f);
    const ull C1_2 = pack2(0.0356774081f, 0.0356774081f);
    const ull HF_2 = pack2(0.5f, 0.5f);

    const float* hvTb = g_hvT + (size_t)(head*B_ + b)*H_*S_;
    const ull*   hdw  = hd2_s + w*H_;
    const float* hp0  = hvT_s + 4*lane;
    float sc[16];

    for (int tile = 0; tile < 4; tile++){
        // stage transposed tile [h][128 j]
        for (int r = w; r < H_; r += 8){
            float4 v = *(const float4*)(hvTb + r*S_ + tile*128 + 4*lane);
            *(float4*)(hvT_s + r*132 + 4*lane) = v;
        }
        __syncthreads();

        ull s01 = 0, q01 = 0, d01 = 0;   // 0x0 == packed (0.f, 0.f)
        ull s23 = 0, q23 = 0, d23 = 0;
        #pragma unroll 8
        for (int h = 0; h < H_; h++){
            ulonglong2 vv = *(const ulonglong2*)(hp0 + h*132);
            ull dd2 = hdw[h];
            ull c2  = c2_s[h];
            ull xa = add2(vv.x, dd2);
            ull xb = add2(vv.y, dd2);
            ull ga = gelu2(xa, C0_2, C1_2, HF_2);
            ull gb = gelu2(xb, C0_2, C1_2, HF_2);
            s01 = add2(s01, ga); q01 = fma2(ga, ga, q01); d01 = fma2(ga, c2, d01);
            s23 = add2(s23, gb); q23 = fma2(gb, gb, q23); d23 = fma2(gb, c2, d23);
        }
        {
            float2 sA = unpack2(s01), sB = unpack2(s23);
            float2 qA = unpack2(q01), qB = unpack2(q23);
            float2 dA = unpack2(d01), dB = unpack2(d23);
            float sarr[4] = {sA.x, sA.y, sB.x, sB.y};
            float qarr[4] = {qA.x, qA.y, qB.x, qB.y};
            float darr[4] = {dA.x, dA.y, dB.x, dB.y};
            #pragma unroll
            for (int q = 0; q < 4; q++){
                float mn = sarr[q]*(1.f/128.f);
                float vr = fmaf(-mn, mn, qarr[q]*(1.f/128.f));
                float rs = rsqrtf(vr + 1e-5f);
                sc[tile*4+q] = rs*fmaf(-mn, C1, darr[q]) + Cb;
            }
        }
        __syncthreads();
    }

    // per-warp log_softmax over the 512 scores of row i
    float mx = sc[0];
    #pragma unroll
    for (int k = 1; k < 16; k++) mx = fmaxf(mx, sc[k]);
    #pragma unroll
    for (int off = 16; off; off >>= 1)
        mx = fmaxf(mx, __shfl_xor_sync(0xffffffffu, mx, off));
    float se = 0.f;
    #pragma unroll
    for (int k = 0; k < 16; k++) se += __expf(sc[k] - mx);
    #pragma unroll
    for (int off = 16; off; off >>= 1)
        se += __shfl_xor_sync(0xffffffffu, se, off);
    float lse = mx + __logf(se);

    float* orow = out + ACT_SZ + (size_t)head*PTR_SZ + (size_t)(b*S_ + i0 + w)*S_;
    #pragma unroll
    for (int tile = 0; tile < 4; tile++){
        float4 o;
        o.x = sc[tile*4+0] - lse;
        o.y = sc[tile*4+1] - lse;
        o.z = sc[tile*4+2] - lse;
        o.w = sc[tile*4+3] - lse;
        *(float4*)(orow + tile*128 + 4*lane) = o;
    }
}

// ---------------------------------------------------------------------------
extern "C" void kernel_launch(void* const* d_in, const int* in_sizes, int n_in,
                              void* d_out, int out_size)
{
    const float* hiddens = (const float*)d_in[0];
    const float* aw1     = (const float*)d_in[1];
    const float* ab1     = (const float*)d_in[2];
    const float* a_ln_g  = (const float*)d_in[3];
    const float* a_ln_b  = (const float*)d_in[4];
    const float* aw2     = (const float*)d_in[5];
    const float* ab2     = (const float*)d_in[6];
    const float* lhid_w  = (const float*)d_in[7];
    const float* lhid_b  = (const float*)d_in[8];
    const float* lhead_w = (const float*)d_in[9];
    const float* lhead_b = (const float*)d_in[10];
    const float* l_ln_g  = (const float*)d_in[11];
    const float* l_ln_b  = (const float*)d_in[12];
    const float* l_pw    = (const float*)d_in[13];
    const float* l_pb    = (const float*)d_in[14];
    const float* rhid_w  = (const float*)d_in[15];
    const float* rhid_b  = (const float*)d_in[16];
    const float* rhead_w = (const float*)d_in[17];
    const float* rhead_b = (const float*)d_in[18];
    const float* r_ln_g  = (const float*)d_in[19];
    const float* r_ln_b  = (const float*)d_in[20];
    const float* r_pw    = (const float*)d_in[21];
    const float* r_pb    = (const float*)d_in[22];
    float* out = (float*)d_out;

    size_t smemC = (size_t)(128*132*4 + 8*H_*8 + H_*8 + 10*4); // ~76.9 KB
    cudaFuncSetAttribute(k_pointer, cudaFuncAttributeMaxDynamicSharedMemorySize, (int)smemC);

    k_linear<<<dim3(5,64), 128>>>(hiddens, aw1, ab1, a_ln_g, a_ln_b,
                                  lhid_w, lhid_b, lhead_w, lhead_b,
                                  rhid_w, rhid_b, rhead_w, rhead_b);
    k_logits<<<128, 256>>>(aw2, ab2);
    k_actsm<<<B_*A_, 512>>>(out);
    k_pointer<<<dim3(64, B_, 2), 256, smemC>>>(l_ln_g, l_ln_b, l_pw, l_pb,
                                               r_ln_g, r_ln_b, r_pw, r_pb, out);
}